// round 2
// baseline (speedup 1.0000x reference)
#include <cuda_runtime.h>
#include <math.h>

#define S_LEN 1024
#define NHEADS 128
#define DQd 192
#define DNd 128
#define DVd 128
#define DMODEL 7168
#define QLORA 1536
#define KVLORA 512

// Scratch (allocation-free rule: __device__ globals)
__device__ float g_qlat[(size_t)S_LEN * QLORA];
__device__ float g_kvlat[(size_t)S_LEN * KVLORA];
__device__ float g_q[(size_t)S_LEN * NHEADS * DQd];
__device__ float g_k[(size_t)S_LEN * NHEADS * DQd];
__device__ float g_v[(size_t)S_LEN * NHEADS * DVd];
__device__ float g_scores[(size_t)NHEADS * S_LEN * S_LEN];
__device__ float g_attnout[(size_t)S_LEN * NHEADS * DVd];

// C[M,N] = A[M,K] @ op(B). BT=true: B is [N,K] row-major (NT). BT=false: B is [K,N] row-major (NN).
// Requires M,N % 128 == 0, K % 8 == 0, all pointers 16B aligned per row tile.
template <bool BT>
__global__ __launch_bounds__(256) void gemm128(
    const float* __restrict__ Ag, const float* __restrict__ Bg, float* __restrict__ Cg,
    int K, int lda, int ldb, int ldc,
    long sA, long sB, long sC)
{
    __shared__ float As[8][128];
    __shared__ float Bs[8][128];

    const float* A = Ag + (long)blockIdx.z * sA;
    const float* B = Bg + (long)blockIdx.z * sB;
    float*       C = Cg + (long)blockIdx.z * sC;

    const int m0 = blockIdx.y * 128;
    const int n0 = blockIdx.x * 128;
    const int t  = threadIdx.x;
    const int tx = t & 15;
    const int ty = t >> 4;
    const int arow = t >> 1;        // 0..127
    const int acol = (t & 1) * 4;   // 0 or 4
    const int brow = t >> 5;        // 0..7   (NN)
    const int bcol = (t & 31) * 4;  // 0..124 (NN)

    const float* Ap = A + (long)(m0 + arow) * lda + acol;
    const float* Bp;
    if (BT) Bp = B + (long)(n0 + arow) * ldb + acol;
    else    Bp = B + (long)brow * ldb + n0 + bcol;

    float acc[2][4][2][4];
#pragma unroll
    for (int a = 0; a < 2; ++a)
#pragma unroll
        for (int i = 0; i < 4; ++i)
#pragma unroll
            for (int b = 0; b < 2; ++b)
#pragma unroll
                for (int j = 0; j < 4; ++j) acc[a][i][b][j] = 0.f;

    for (int k0 = 0; k0 < K; k0 += 8) {
        float4 av = *(const float4*)(Ap + k0);
        float4 bv;
        if (BT) bv = *(const float4*)(Bp + k0);
        else    bv = *(const float4*)(Bp + (long)k0 * ldb);

        __syncthreads();
        As[acol + 0][arow] = av.x;
        As[acol + 1][arow] = av.y;
        As[acol + 2][arow] = av.z;
        As[acol + 3][arow] = av.w;
        if (BT) {
            Bs[acol + 0][arow] = bv.x;
            Bs[acol + 1][arow] = bv.y;
            Bs[acol + 2][arow] = bv.z;
            Bs[acol + 3][arow] = bv.w;
        } else {
            *(float4*)&Bs[brow][bcol] = bv;
        }
        __syncthreads();

#pragma unroll
        for (int k = 0; k < 8; ++k) {
            float4 a0 = *(const float4*)&As[k][ty * 4];
            float4 a1 = *(const float4*)&As[k][64 + ty * 4];
            float4 b0 = *(const float4*)&Bs[k][tx * 4];
            float4 b1 = *(const float4*)&Bs[k][64 + tx * 4];
            float ar[8] = {a0.x, a0.y, a0.z, a0.w, a1.x, a1.y, a1.z, a1.w};
            float br[8] = {b0.x, b0.y, b0.z, b0.w, b1.x, b1.y, b1.z, b1.w};
#pragma unroll
            for (int a = 0; a < 2; ++a)
#pragma unroll
                for (int i = 0; i < 4; ++i)
#pragma unroll
                    for (int b = 0; b < 2; ++b)
#pragma unroll
                        for (int j = 0; j < 4; ++j)
                            acc[a][i][b][j] = fmaf(ar[a * 4 + i], br[b * 4 + j], acc[a][i][b][j]);
        }
    }

#pragma unroll
    for (int a = 0; a < 2; ++a)
#pragma unroll
        for (int i = 0; i < 4; ++i) {
            int m = m0 + a * 64 + ty * 4 + i;
#pragma unroll
            for (int b = 0; b < 2; ++b) {
                float4 o;
                o.x = acc[a][i][b][0];
                o.y = acc[a][i][b][1];
                o.z = acc[a][i][b][2];
                o.w = acc[a][i][b][3];
                *(float4*)(C + (long)m * ldc + n0 + b * 64 + tx * 4) = o;
            }
        }
}

// Interleaved RoPE over dims [128,192) of each head vector. X: [S][H][192].
__global__ void rope_kernel(float* __restrict__ X)
{
    long idx = (long)blockIdx.x * blockDim.x + threadIdx.x;
    if (idx >= (long)S_LEN * NHEADS * 32) return;
    int i = (int)(idx & 31);
    int h = (int)((idx >> 5) & (NHEADS - 1));
    int s = (int)(idx >> 12);

    int m = (2 * i) & 31;  // emb[2i] = pos * inv_freq[(2i) mod 32]
    float invf = (float)pow(10000.0, -(double)m / 32.0);
    float ang = (float)s * invf;
    float sn, cs;
    sincosf(ang, &sn, &cs);

    float* p = X + ((long)s * NHEADS + h) * DQd + DNd + 2 * i;
    float x1 = p[0], x2 = p[1];
    p[0] = x1 * cs - x2 * sn;
    p[1] = x1 * sn + x2 * cs;
}

// Row softmax with 1/sqrt(192) pre-scale. One block per row of length 1024.
__global__ __launch_bounds__(256) void softmax_kernel(float* __restrict__ P)
{
    float* row = P + (long)blockIdx.x * S_LEN;
    const int t = threadIdx.x;
    const int lane = t & 31, wid = t >> 5;
    const float scale = 0.07216878364870323f;  // 1/sqrt(192)

    float4 v = *(float4*)(row + t * 4);
    v.x *= scale; v.y *= scale; v.z *= scale; v.w *= scale;

    __shared__ float red[8];
    float lm = fmaxf(fmaxf(v.x, v.y), fmaxf(v.z, v.w));
#pragma unroll
    for (int o = 16; o; o >>= 1) lm = fmaxf(lm, __shfl_xor_sync(0xffffffffu, lm, o));
    if (lane == 0) red[wid] = lm;
    __syncthreads();
    float mall = red[0];
#pragma unroll
    for (int i = 1; i < 8; ++i) mall = fmaxf(mall, red[i]);

    float e0 = __expf(v.x - mall);
    float e1 = __expf(v.y - mall);
    float e2 = __expf(v.z - mall);
    float e3 = __expf(v.w - mall);
    float ls = e0 + e1 + e2 + e3;
#pragma unroll
    for (int o = 16; o; o >>= 1) ls += __shfl_xor_sync(0xffffffffu, ls, o);
    __syncthreads();
    if (lane == 0) red[wid] = ls;
    __syncthreads();
    float sall = 0.f;
#pragma unroll
    for (int i = 0; i < 8; ++i) sall += red[i];
    float inv = 1.f / sall;

    float4 o4 = make_float4(e0 * inv, e1 * inv, e2 * inv, e3 * inv);
    *(float4*)(row + t * 4) = o4;
}

extern "C" void kernel_launch(void* const* d_in, const int* in_sizes, int n_in,
                              void* d_out, int out_size)
{
    const float* X    = (const float*)d_in[0];  // [1024, 7168]
    const float* Wqa  = (const float*)d_in[1];  // [1536, 7168]
    const float* Wkva = (const float*)d_in[2];  // [512, 7168]
    const float* Wqb  = (const float*)d_in[3];  // [24576, 1536]
    const float* Wkb  = (const float*)d_in[4];  // [24576, 512]
    const float* Wvb  = (const float*)d_in[5];  // [16384, 512]
    const float* Wo   = (const float*)d_in[6];  // [7168, 16384]
    float* out = (float*)d_out;                 // [1024, 7168]

    float *qlat, *kvlat, *q, *k, *v, *sc, *ao;
    cudaGetSymbolAddress((void**)&qlat, g_qlat);
    cudaGetSymbolAddress((void**)&kvlat, g_kvlat);
    cudaGetSymbolAddress((void**)&q, g_q);
    cudaGetSymbolAddress((void**)&k, g_k);
    cudaGetSymbolAddress((void**)&v, g_v);
    cudaGetSymbolAddress((void**)&sc, g_scores);
    cudaGetSymbolAddress((void**)&ao, g_attnout);

    const dim3 blk(256);
    const int EQ = NHEADS * DQd;   // 24576
    const int EV = NHEADS * DVd;   // 16384

    // q_lat = X @ Wqa^T      [1024, 1536]
    gemm128<true><<<dim3(QLORA / 128, S_LEN / 128, 1), blk>>>(
        X, Wqa, qlat, DMODEL, DMODEL, DMODEL, QLORA, 0, 0, 0);
    // kv_lat = X @ Wkva^T    [1024, 512]
    gemm128<true><<<dim3(KVLORA / 128, S_LEN / 128, 1), blk>>>(
        X, Wkva, kvlat, DMODEL, DMODEL, DMODEL, KVLORA, 0, 0, 0);
    // q = q_lat @ Wqb^T      [1024, 24576]
    gemm128<true><<<dim3(EQ / 128, S_LEN / 128, 1), blk>>>(
        qlat, Wqb, q, QLORA, QLORA, QLORA, EQ, 0, 0, 0);
    // k = kv_lat @ Wkb^T     [1024, 24576]
    gemm128<true><<<dim3(EQ / 128, S_LEN / 128, 1), blk>>>(
        kvlat, Wkb, k, KVLORA, KVLORA, KVLORA, EQ, 0, 0, 0);
    // v = kv_lat @ Wvb^T     [1024, 16384]
    gemm128<true><<<dim3(EV / 128, S_LEN / 128, 1), blk>>>(
        kvlat, Wvb, v, KVLORA, KVLORA, KVLORA, EV, 0, 0, 0);

    // RoPE on q and k rope sections
    rope_kernel<<<(S_LEN * NHEADS * 32) / 256, 256>>>(q);
    rope_kernel<<<(S_LEN * NHEADS * 32) / 256, 256>>>(k);

    // scores[h] = q_h @ k_h^T   (batched over 128 heads)
    gemm128<true><<<dim3(S_LEN / 128, S_LEN / 128, NHEADS), blk>>>(
        q, k, sc, DQd, EQ, EQ, S_LEN,
        (long)DQd, (long)DQd, (long)S_LEN * S_LEN);

    // softmax over each score row (scale fused)
    softmax_kernel<<<NHEADS * S_LEN, 256>>>(sc);

    // attn_out[h] = P_h @ v_h   (batched, NN)
    gemm128<false><<<dim3(DVd / 128, S_LEN / 128, NHEADS), blk>>>(
        sc, v, ao, S_LEN, S_LEN, EV, EV,
        (long)S_LEN * S_LEN, (long)DVd, (long)DVd);

    // out = attn_out @ Wo^T   [1024, 7168]
    gemm128<true><<<dim3(DMODEL / 128, S_LEN / 128, 1), blk>>>(
        ao, Wo, out, EV, EV, EV, DMODEL, 0, 0, 0);
}

// round 3
// speedup vs baseline: 1.8923x; 1.8923x over previous
#include <cuda_runtime.h>
#include <math.h>

#define S_LEN 1024
#define NHEADS 128
#define DQd 192
#define DNd 128
#define DVd 128
#define DMODEL 7168
#define QLORA 1536
#define KVLORA 512

// Scratch (allocation-free rule: __device__ globals)
__device__ float g_qlat[(size_t)S_LEN * QLORA];
__device__ float g_kvlat[(size_t)S_LEN * KVLORA];
__device__ float g_q[(size_t)S_LEN * NHEADS * DQd];
__device__ float g_k[(size_t)S_LEN * NHEADS * DQd];
__device__ float g_v[(size_t)S_LEN * NHEADS * DVd];
__device__ float g_scores[(size_t)NHEADS * S_LEN * S_LEN];
__device__ float g_attnout[(size_t)S_LEN * NHEADS * DVd];

__device__ __forceinline__ unsigned f2tf32(float x) {
    unsigned u;
    asm("cvt.rna.tf32.f32 %0, %1;" : "=r"(u) : "f"(x));
    return u;
}

__device__ __forceinline__ void mma_tf32(float* d, const unsigned* a, const unsigned* b) {
    asm volatile(
        "mma.sync.aligned.m16n8k8.row.col.f32.tf32.tf32.f32 "
        "{%0,%1,%2,%3}, {%4,%5,%6,%7}, {%8,%9}, {%0,%1,%2,%3};"
        : "+f"(d[0]), "+f"(d[1]), "+f"(d[2]), "+f"(d[3])
        : "r"(a[0]), "r"(a[1]), "r"(a[2]), "r"(a[3]), "r"(b[0]), "r"(b[1]));
}

// C[M,N] = A[M,K] @ op(B) via tf32 tensor-core MMA, fp32 accumulate.
// BT=true: B is [N,K] row-major (NT). BT=false: B is [K,N] row-major (NN).
// M % 128 == 0, N % 128 == 0, K % 32 == 0.
#define LDS_S 36  // smem row stride (floats): bank = 4*row + col (mod 32) -> conflict-free frags
template <bool BT>
__global__ __launch_bounds__(256, 1) void gemm_tf32(
    const float* __restrict__ Ag, const float* __restrict__ Bg, float* __restrict__ Cg,
    int K, int lda, int ldb, int ldc,
    long sA, long sB, long sC)
{
    __shared__ float As[128][LDS_S];
    __shared__ float Bs[128][LDS_S];

    const float* A = Ag + (long)blockIdx.z * sA;
    const float* B = Bg + (long)blockIdx.z * sB;
    float*       C = Cg + (long)blockIdx.z * sC;

    const int m0 = blockIdx.y * 128;
    const int n0 = blockIdx.x * 128;
    const int t  = threadIdx.x;
    const int wid = t >> 5, lane = t & 31;
    const int wm = wid >> 1;       // 0..3 -> 32-row slab
    const int wn = wid & 1;        // 0..1 -> 64-col slab
    const int g  = lane >> 2;      // 0..7
    const int tg = lane & 3;       // 0..3

    // gmem tile mapping: A tile 128x32, each thread 4 x float4
    const int ar_row = t >> 1;     // 0..127
    const int ar_c   = t & 1;      // float4 col parity
    const float* Ap = A + (long)(m0 + ar_row) * lda + ar_c * 4;

    // B tile: BT -> rows are N (128x32); NN -> rows are K (32x128)
    const int bt_row = t >> 1, bt_c = t & 1;       // BT
    const int nn_kr  = t >> 3, nn_c = t & 7;       // NN
    const float* Bp;
    if (BT) Bp = B + (long)(n0 + bt_row) * ldb + bt_c * 4;
    else    Bp = B + (long)nn_kr * ldb + n0 + nn_c * 4;

    float acc[2][8][4];
#pragma unroll
    for (int mt = 0; mt < 2; ++mt)
#pragma unroll
        for (int nt = 0; nt < 8; ++nt)
#pragma unroll
            for (int j = 0; j < 4; ++j) acc[mt][nt][j] = 0.f;

    float4 ar[4], br[4];
    // prefetch tile 0
#pragma unroll
    for (int i = 0; i < 4; ++i) ar[i] = *(const float4*)(Ap + 8 * i);
#pragma unroll
    for (int i = 0; i < 4; ++i) {
        if (BT) br[i] = *(const float4*)(Bp + 8 * i);
        else    br[i] = *(const float4*)(Bp + 32 * i);
    }

    for (int k0 = 0; k0 < K; k0 += 32) {
        __syncthreads();  // previous compute done before overwriting smem
        // store (with rna tf32 rounding)
#pragma unroll
        for (int i = 0; i < 4; ++i) {
            unsigned* d = (unsigned*)&As[ar_row][(ar_c + 2 * i) * 4];
            d[0] = f2tf32(ar[i].x); d[1] = f2tf32(ar[i].y);
            d[2] = f2tf32(ar[i].z); d[3] = f2tf32(ar[i].w);
        }
        if (BT) {
#pragma unroll
            for (int i = 0; i < 4; ++i) {
                unsigned* d = (unsigned*)&Bs[bt_row][(bt_c + 2 * i) * 4];
                d[0] = f2tf32(br[i].x); d[1] = f2tf32(br[i].y);
                d[2] = f2tf32(br[i].z); d[3] = f2tf32(br[i].w);
            }
        } else {
#pragma unroll
            for (int i = 0; i < 4; ++i) {
                int nb = (nn_c + 8 * i) * 4;
                ((unsigned*)&Bs[nb + 0][nn_kr])[0] = f2tf32(br[i].x);
                ((unsigned*)&Bs[nb + 1][nn_kr])[0] = f2tf32(br[i].y);
                ((unsigned*)&Bs[nb + 2][nn_kr])[0] = f2tf32(br[i].z);
                ((unsigned*)&Bs[nb + 3][nn_kr])[0] = f2tf32(br[i].w);
            }
        }
        __syncthreads();

        // prefetch next tile (overlaps with compute below)
        if (k0 + 32 < K) {
#pragma unroll
            for (int i = 0; i < 4; ++i) ar[i] = *(const float4*)(Ap + k0 + 32 + 8 * i);
#pragma unroll
            for (int i = 0; i < 4; ++i) {
                if (BT) br[i] = *(const float4*)(Bp + k0 + 32 + 8 * i);
                else    br[i] = *(const float4*)(Bp + (long)(k0 + 32) * ldb + 32 * i);
            }
        }

        // compute 4 k-chunks of 8
#pragma unroll
        for (int kc = 0; kc < 4; ++kc) {
            const int kb = kc * 8;
            unsigned af[2][4];
#pragma unroll
            for (int mt = 0; mt < 2; ++mt) {
                const int r = wm * 32 + mt * 16 + g;
                af[mt][0] = __float_as_uint(As[r][kb + tg]);
                af[mt][1] = __float_as_uint(As[r + 8][kb + tg]);
                af[mt][2] = __float_as_uint(As[r][kb + tg + 4]);
                af[mt][3] = __float_as_uint(As[r + 8][kb + tg + 4]);
            }
#pragma unroll
            for (int nt = 0; nt < 8; ++nt) {
                const int n = wn * 64 + nt * 8 + g;
                unsigned bf[2];
                bf[0] = __float_as_uint(Bs[n][kb + tg]);
                bf[1] = __float_as_uint(Bs[n][kb + tg + 4]);
                mma_tf32(acc[0][nt], af[0], bf);
                mma_tf32(acc[1][nt], af[1], bf);
            }
        }
    }

    // epilogue
#pragma unroll
    for (int mt = 0; mt < 2; ++mt) {
        const int rr = m0 + wm * 32 + mt * 16 + g;
#pragma unroll
        for (int nt = 0; nt < 8; ++nt) {
            const int cc = n0 + wn * 64 + nt * 8 + tg * 2;
            *(float2*)(C + (long)rr * ldc + cc)       = make_float2(acc[mt][nt][0], acc[mt][nt][1]);
            *(float2*)(C + (long)(rr + 8) * ldc + cc) = make_float2(acc[mt][nt][2], acc[mt][nt][3]);
        }
    }
}

// Interleaved RoPE over dims [128,192) of each head vector. X: [S][H][192].
__global__ void rope_kernel(float* __restrict__ X)
{
    long idx = (long)blockIdx.x * blockDim.x + threadIdx.x;
    if (idx >= (long)S_LEN * NHEADS * 32) return;
    int i = (int)(idx & 31);
    int h = (int)((idx >> 5) & (NHEADS - 1));
    int s = (int)(idx >> 12);

    int m = (2 * i) & 31;  // emb[2i] = pos * inv_freq[(2i) mod 32]
    float invf = (float)pow(10000.0, -(double)m / 32.0);
    float ang = (float)s * invf;
    float sn, cs;
    sincosf(ang, &sn, &cs);

    float* p = X + ((long)s * NHEADS + h) * DQd + DNd + 2 * i;
    float x1 = p[0], x2 = p[1];
    p[0] = x1 * cs - x2 * sn;
    p[1] = x1 * sn + x2 * cs;
}

// Row softmax with 1/sqrt(192) pre-scale. One block per row of length 1024.
__global__ __launch_bounds__(256) void softmax_kernel(float* __restrict__ P)
{
    float* row = P + (long)blockIdx.x * S_LEN;
    const int t = threadIdx.x;
    const int lane = t & 31, wid = t >> 5;
    const float scale = 0.07216878364870323f;  // 1/sqrt(192)

    float4 v = *(float4*)(row + t * 4);
    v.x *= scale; v.y *= scale; v.z *= scale; v.w *= scale;

    __shared__ float red[8];
    float lm = fmaxf(fmaxf(v.x, v.y), fmaxf(v.z, v.w));
#pragma unroll
    for (int o = 16; o; o >>= 1) lm = fmaxf(lm, __shfl_xor_sync(0xffffffffu, lm, o));
    if (lane == 0) red[wid] = lm;
    __syncthreads();
    float mall = red[0];
#pragma unroll
    for (int i = 1; i < 8; ++i) mall = fmaxf(mall, red[i]);

    float e0 = __expf(v.x - mall);
    float e1 = __expf(v.y - mall);
    float e2 = __expf(v.z - mall);
    float e3 = __expf(v.w - mall);
    float ls = e0 + e1 + e2 + e3;
#pragma unroll
    for (int o = 16; o; o >>= 1) ls += __shfl_xor_sync(0xffffffffu, ls, o);
    __syncthreads();
    if (lane == 0) red[wid] = ls;
    __syncthreads();
    float sall = 0.f;
#pragma unroll
    for (int i = 0; i < 8; ++i) sall += red[i];
    float inv = 1.f / sall;

    float4 o4 = make_float4(e0 * inv, e1 * inv, e2 * inv, e3 * inv);
    *(float4*)(row + t * 4) = o4;
}

extern "C" void kernel_launch(void* const* d_in, const int* in_sizes, int n_in,
                              void* d_out, int out_size)
{
    const float* X    = (const float*)d_in[0];  // [1024, 7168]
    const float* Wqa  = (const float*)d_in[1];  // [1536, 7168]
    const float* Wkva = (const float*)d_in[2];  // [512, 7168]
    const float* Wqb  = (const float*)d_in[3];  // [24576, 1536]
    const float* Wkb  = (const float*)d_in[4];  // [24576, 512]
    const float* Wvb  = (const float*)d_in[5];  // [16384, 512]
    const float* Wo   = (const float*)d_in[6];  // [7168, 16384]
    float* out = (float*)d_out;                 // [1024, 7168]

    float *qlat, *kvlat, *q, *k, *v, *sc, *ao;
    cudaGetSymbolAddress((void**)&qlat, g_qlat);
    cudaGetSymbolAddress((void**)&kvlat, g_kvlat);
    cudaGetSymbolAddress((void**)&q, g_q);
    cudaGetSymbolAddress((void**)&k, g_k);
    cudaGetSymbolAddress((void**)&v, g_v);
    cudaGetSymbolAddress((void**)&sc, g_scores);
    cudaGetSymbolAddress((void**)&ao, g_attnout);

    const dim3 blk(256);
    const int EQ = NHEADS * DQd;   // 24576
    const int EV = NHEADS * DVd;   // 16384

    // q_lat = X @ Wqa^T      [1024, 1536]
    gemm_tf32<true><<<dim3(QLORA / 128, S_LEN / 128, 1), blk>>>(
        X, Wqa, qlat, DMODEL, DMODEL, DMODEL, QLORA, 0, 0, 0);
    // kv_lat = X @ Wkva^T    [1024, 512]
    gemm_tf32<true><<<dim3(KVLORA / 128, S_LEN / 128, 1), blk>>>(
        X, Wkva, kvlat, DMODEL, DMODEL, DMODEL, KVLORA, 0, 0, 0);
    // q = q_lat @ Wqb^T      [1024, 24576]
    gemm_tf32<true><<<dim3(EQ / 128, S_LEN / 128, 1), blk>>>(
        qlat, Wqb, q, QLORA, QLORA, QLORA, EQ, 0, 0, 0);
    // k = kv_lat @ Wkb^T     [1024, 24576]
    gemm_tf32<true><<<dim3(EQ / 128, S_LEN / 128, 1), blk>>>(
        kvlat, Wkb, k, KVLORA, KVLORA, KVLORA, EQ, 0, 0, 0);
    // v = kv_lat @ Wvb^T     [1024, 16384]
    gemm_tf32<true><<<dim3(EV / 128, S_LEN / 128, 1), blk>>>(
        kvlat, Wvb, v, KVLORA, KVLORA, KVLORA, EV, 0, 0, 0);

    // RoPE on q and k rope sections
    rope_kernel<<<(S_LEN * NHEADS * 32) / 256, 256>>>(q);
    rope_kernel<<<(S_LEN * NHEADS * 32) / 256, 256>>>(k);

    // scores[h] = q_h @ k_h^T   (batched over 128 heads, K=192)
    gemm_tf32<true><<<dim3(S_LEN / 128, S_LEN / 128, NHEADS), blk>>>(
        q, k, sc, DQd, EQ, EQ, S_LEN,
        (long)DQd, (long)DQd, (long)S_LEN * S_LEN);

    // softmax over each score row (scale fused)
    softmax_kernel<<<NHEADS * S_LEN, 256>>>(sc);

    // attn_out[h] = P_h @ v_h   (batched, NN)
    gemm_tf32<false><<<dim3(DVd / 128, S_LEN / 128, NHEADS), blk>>>(
        sc, v, ao, S_LEN, S_LEN, EV, EV,
        (long)S_LEN * S_LEN, (long)DVd, (long)DVd);

    // out = attn_out @ Wo^T   [1024, 7168]
    gemm_tf32<true><<<dim3(DMODEL / 128, S_LEN / 128, 1), blk>>>(
        ao, Wo, out, EV, EV, EV, DMODEL, 0, 0, 0);
}

// round 4
// speedup vs baseline: 2.3383x; 1.2357x over previous
#include <cuda_runtime.h>
#include <math.h>
#include <stdint.h>

#define S_LEN 1024
#define NHEADS 128
#define DQd 192
#define DNd 128
#define DVd 128
#define DMODEL 7168
#define QLORA 1536
#define KVLORA 512

// Scratch (allocation-free rule: __device__ globals)
__device__ float g_xr[(size_t)S_LEN * DMODEL];          // tf32-rounded hidden_states
__device__ float g_wvbr[(size_t)NHEADS * DVd * KVLORA]; // tf32-rounded Wvb
__device__ float g_qlat[(size_t)S_LEN * QLORA];
__device__ float g_kvlat[(size_t)S_LEN * KVLORA];
__device__ float g_q[(size_t)S_LEN * NHEADS * DQd];
__device__ float g_k[(size_t)S_LEN * NHEADS * DQd];
__device__ float g_vt[(size_t)NHEADS * DVd * S_LEN];    // V transposed: [h*128+d][s]
__device__ float g_scores[(size_t)NHEADS * S_LEN * S_LEN];
__device__ float g_attnout[(size_t)S_LEN * NHEADS * DVd];

__device__ __forceinline__ unsigned f2tf32(float x) {
    unsigned u;
    asm("cvt.rna.tf32.f32 %0, %1;" : "=r"(u) : "f"(x));
    return u;
}
__device__ __forceinline__ float f2tf32f(float x) { return __uint_as_float(f2tf32(x)); }

__device__ __forceinline__ void mma_tf32(float* d, const unsigned* a, const unsigned* b) {
    asm volatile(
        "mma.sync.aligned.m16n8k8.row.col.f32.tf32.tf32.f32 "
        "{%0,%1,%2,%3}, {%4,%5,%6,%7}, {%8,%9}, {%0,%1,%2,%3};"
        : "+f"(d[0]), "+f"(d[1]), "+f"(d[2]), "+f"(d[3])
        : "r"(a[0]), "r"(a[1]), "r"(a[2]), "r"(a[3]), "r"(b[0]), "r"(b[1]));
}

__device__ __forceinline__ void cp_async16(uint32_t dst, const void* src) {
    asm volatile("cp.async.cg.shared.global [%0], [%1], 16;\n" :: "r"(dst), "l"(src));
}
#define CP_COMMIT() asm volatile("cp.async.commit_group;\n" ::: "memory")
#define CP_WAIT0()  asm volatile("cp.async.wait_group 0;\n" ::: "memory")

// ---------------------------------------------------------------------------
// C[M,N] = A[M,K] @ B^T, B is [N,K] row-major. tf32 MMA, fp32 accumulate.
// A must be tf32-pre-rounded in gmem (cp.async path). B is rounded at staging.
// M,N % 128 == 0, K % 32 == 0. Double-buffered, 1 sync/iter, 2 CTAs/SM.
// Dynamic smem: As[2][128][36] + Bs[2][128][36] floats = 73728 B.
// ---------------------------------------------------------------------------
#define SROW 36
#define SBUF (128 * SROW)

template <bool ROUND>
__global__ __launch_bounds__(256, 2) void gemm_nt(
    const float* __restrict__ Ag, const float* __restrict__ Bg, float* __restrict__ Cg,
    int K, int lda, int ldb, int ldc, long sA, long sB, long sC)
{
    extern __shared__ float sm[];
    float* SA = sm;              // [2][128][36]
    float* SB = sm + 2 * SBUF;   // [2][128][36]

    const float* A = Ag + (long)blockIdx.z * sA;
    const float* B = Bg + (long)blockIdx.z * sB;
    float*       C = Cg + (long)blockIdx.z * sC;

    const int m0 = blockIdx.y * 128;
    const int n0 = blockIdx.x * 128;
    const int t = threadIdx.x, wid = t >> 5, lane = t & 31;
    const int wm = wid >> 1, wn = wid & 1;
    const int g = lane >> 2, tg = lane & 3;

    // staging mapping: row = t>>1 (0..127), float4-col = (t&1) + 2i (i=0..3)
    const int srow = t >> 1;
    const int sc4  = t & 1;
    const float* Ap = A + (long)(m0 + srow) * lda + sc4 * 4;
    const float* Bp = B + (long)(n0 + srow) * ldb + sc4 * 4;

    float acc[2][8][4] = {};

    float4 br[4];
#pragma unroll
    for (int i = 0; i < 4; ++i) br[i] = *(const float4*)(Bp + 8 * i);
#pragma unroll
    for (int i = 0; i < 4; ++i)
        cp_async16((uint32_t)__cvta_generic_to_shared(&SA[srow * SROW + (sc4 + 2 * i) * 4]),
                   Ap + 8 * i);
    CP_COMMIT();

    const int niter = K >> 5;
    for (int it = 0; it < niter; ++it) {
        const int cur = it & 1;
        const float* sa = SA + cur * SBUF;
        float*       sb = SB + cur * SBUF;

        // store B(it) (tf32-rounded)
#pragma unroll
        for (int i = 0; i < 4; ++i) {
            uint4 u;
            u.x = f2tf32(br[i].x); u.y = f2tf32(br[i].y);
            u.z = f2tf32(br[i].z); u.w = f2tf32(br[i].w);
            *(uint4*)&sb[srow * SROW + (sc4 + 2 * i) * 4] = u;
        }
        CP_WAIT0();
        __syncthreads();

        // prefetch tile it+1 (overlaps with compute below)
        if (it + 1 < niter) {
            const int k0 = (it + 1) << 5;
#pragma unroll
            for (int i = 0; i < 4; ++i) br[i] = *(const float4*)(Bp + k0 + 8 * i);
            float* sa2 = SA + (cur ^ 1) * SBUF;
#pragma unroll
            for (int i = 0; i < 4; ++i)
                cp_async16((uint32_t)__cvta_generic_to_shared(&sa2[srow * SROW + (sc4 + 2 * i) * 4]),
                           Ap + k0 + 8 * i);
            CP_COMMIT();
        }

        // compute 4 k-chunks of 8
#pragma unroll
        for (int kc = 0; kc < 4; ++kc) {
            const int kb = kc * 8;
            unsigned af[2][4];
#pragma unroll
            for (int mt = 0; mt < 2; ++mt) {
                const int r = wm * 32 + mt * 16 + g;
                af[mt][0] = __float_as_uint(sa[r * SROW + kb + tg]);
                af[mt][1] = __float_as_uint(sa[(r + 8) * SROW + kb + tg]);
                af[mt][2] = __float_as_uint(sa[r * SROW + kb + tg + 4]);
                af[mt][3] = __float_as_uint(sa[(r + 8) * SROW + kb + tg + 4]);
            }
#pragma unroll
            for (int nt = 0; nt < 8; ++nt) {
                const int n = wn * 64 + nt * 8 + g;
                unsigned bf[2];
                bf[0] = __float_as_uint(sb[n * SROW + kb + tg]);
                bf[1] = __float_as_uint(sb[n * SROW + kb + tg + 4]);
                mma_tf32(acc[0][nt], af[0], bf);
                mma_tf32(acc[1][nt], af[1], bf);
            }
        }
    }

    // epilogue (optionally tf32-round C so consumers can cp.async it raw)
#pragma unroll
    for (int mt = 0; mt < 2; ++mt) {
        const int rr = m0 + wm * 32 + mt * 16 + g;
#pragma unroll
        for (int nt = 0; nt < 8; ++nt) {
            const int cc = n0 + wn * 64 + nt * 8 + tg * 2;
            float2 v0 = make_float2(acc[mt][nt][0], acc[mt][nt][1]);
            float2 v1 = make_float2(acc[mt][nt][2], acc[mt][nt][3]);
            if (ROUND) {
                v0.x = f2tf32f(v0.x); v0.y = f2tf32f(v0.y);
                v1.x = f2tf32f(v1.x); v1.y = f2tf32f(v1.y);
            }
            *(float2*)(C + (long)rr * ldc + cc)       = v0;
            *(float2*)(C + (long)(rr + 8) * ldc + cc) = v1;
        }
    }
}

// Elementwise tf32 rounding (for raw A-side inputs: X, Wvb)
__global__ void round_tf32_kernel(const float* __restrict__ in, float* __restrict__ out, int n4)
{
    int i = blockIdx.x * blockDim.x + threadIdx.x;
    if (i >= n4) return;
    float4 v = ((const float4*)in)[i];
    v.x = f2tf32f(v.x); v.y = f2tf32f(v.y); v.z = f2tf32f(v.z); v.w = f2tf32f(v.w);
    ((float4*)out)[i] = v;
}

// Interleaved RoPE over dims [128,192) of each head vector. X: [S][H][192].
// Writes tf32-rounded (consumed by scores GEMM A/B).
__global__ void rope_kernel(float* __restrict__ X)
{
    long idx = (long)blockIdx.x * blockDim.x + threadIdx.x;
    if (idx >= (long)S_LEN * NHEADS * 32) return;
    int i = (int)(idx & 31);
    int h = (int)((idx >> 5) & (NHEADS - 1));
    int s = (int)(idx >> 12);

    int m = (2 * i) & 31;
    float invf = (float)pow(10000.0, -(double)m / 32.0);
    float ang = (float)s * invf;
    float sn, cs;
    sincosf(ang, &sn, &cs);

    float* p = X + ((long)s * NHEADS + h) * DQd + DNd + 2 * i;
    float x1 = p[0], x2 = p[1];
    p[0] = f2tf32f(x1 * cs - x2 * sn);
    p[1] = f2tf32f(x1 * sn + x2 * cs);
}

// Row softmax with 1/sqrt(192) pre-scale; writes tf32-rounded probs.
__global__ __launch_bounds__(256) void softmax_kernel(float* __restrict__ P)
{
    float* row = P + (long)blockIdx.x * S_LEN;
    const int t = threadIdx.x;
    const int lane = t & 31, wid = t >> 5;
    const float scale = 0.07216878364870323f;  // 1/sqrt(192)

    float4 v = *(float4*)(row + t * 4);
    v.x *= scale; v.y *= scale; v.z *= scale; v.w *= scale;

    __shared__ float red[8];
    float lm = fmaxf(fmaxf(v.x, v.y), fmaxf(v.z, v.w));
#pragma unroll
    for (int o = 16; o; o >>= 1) lm = fmaxf(lm, __shfl_xor_sync(0xffffffffu, lm, o));
    if (lane == 0) red[wid] = lm;
    __syncthreads();
    float mall = red[0];
#pragma unroll
    for (int i = 1; i < 8; ++i) mall = fmaxf(mall, red[i]);

    float e0 = __expf(v.x - mall);
    float e1 = __expf(v.y - mall);
    float e2 = __expf(v.z - mall);
    float e3 = __expf(v.w - mall);
    float ls = e0 + e1 + e2 + e3;
#pragma unroll
    for (int o = 16; o; o >>= 1) ls += __shfl_xor_sync(0xffffffffu, ls, o);
    __syncthreads();
    if (lane == 0) red[wid] = ls;
    __syncthreads();
    float sall = 0.f;
#pragma unroll
    for (int i = 0; i < 8; ++i) sall += red[i];
    float inv = 1.f / sall;

    float4 o4 = make_float4(f2tf32f(e0 * inv), f2tf32f(e1 * inv),
                            f2tf32f(e2 * inv), f2tf32f(e3 * inv));
    *(float4*)(row + t * 4) = o4;
}

extern "C" void kernel_launch(void* const* d_in, const int* in_sizes, int n_in,
                              void* d_out, int out_size)
{
    const float* X    = (const float*)d_in[0];  // [1024, 7168]
    const float* Wqa  = (const float*)d_in[1];  // [1536, 7168]
    const float* Wkva = (const float*)d_in[2];  // [512, 7168]
    const float* Wqb  = (const float*)d_in[3];  // [24576, 1536]
    const float* Wkb  = (const float*)d_in[4];  // [24576, 512]
    const float* Wvb  = (const float*)d_in[5];  // [16384, 512]
    const float* Wo   = (const float*)d_in[6];  // [7168, 16384]
    float* out = (float*)d_out;                 // [1024, 7168]

    float *xr, *wvbr, *qlat, *kvlat, *q, *k, *vt, *sc, *ao;
    cudaGetSymbolAddress((void**)&xr, g_xr);
    cudaGetSymbolAddress((void**)&wvbr, g_wvbr);
    cudaGetSymbolAddress((void**)&qlat, g_qlat);
    cudaGetSymbolAddress((void**)&kvlat, g_kvlat);
    cudaGetSymbolAddress((void**)&q, g_q);
    cudaGetSymbolAddress((void**)&k, g_k);
    cudaGetSymbolAddress((void**)&vt, g_vt);
    cudaGetSymbolAddress((void**)&sc, g_scores);
    cudaGetSymbolAddress((void**)&ao, g_attnout);

    const int SMEM = 4 * SBUF * (int)sizeof(float);  // 73728 B
    cudaFuncSetAttribute((const void*)gemm_nt<true>,
                         cudaFuncAttributeMaxDynamicSharedMemorySize, SMEM);
    cudaFuncSetAttribute((const void*)gemm_nt<false>,
                         cudaFuncAttributeMaxDynamicSharedMemorySize, SMEM);

    const dim3 blk(256);
    const int EQ = NHEADS * DQd;   // 24576
    const int EV = NHEADS * DVd;   // 16384

    // tf32-round raw A-side inputs
    {
        int n4x = S_LEN * DMODEL / 4;
        round_tf32_kernel<<<(n4x + 255) / 256, 256>>>(X, xr, n4x);
        int n4v = EV * KVLORA / 4;
        round_tf32_kernel<<<(n4v + 255) / 256, 256>>>(Wvb, wvbr, n4v);
    }

    // q_lat = Xr @ Wqa^T      [1024, 1536]
    gemm_nt<true><<<dim3(QLORA / 128, S_LEN / 128, 1), blk, SMEM>>>(
        xr, Wqa, qlat, DMODEL, DMODEL, DMODEL, QLORA, 0, 0, 0);
    // kv_lat = Xr @ Wkva^T    [1024, 512]
    gemm_nt<true><<<dim3(KVLORA / 128, S_LEN / 128, 1), blk, SMEM>>>(
        xr, Wkva, kvlat, DMODEL, DMODEL, DMODEL, KVLORA, 0, 0, 0);
    // q = q_lat @ Wqb^T       [1024, 24576]
    gemm_nt<true><<<dim3(EQ / 128, S_LEN / 128, 1), blk, SMEM>>>(
        qlat, Wqb, q, QLORA, QLORA, QLORA, EQ, 0, 0, 0);
    // k = kv_lat @ Wkb^T      [1024, 24576]
    gemm_nt<true><<<dim3(EQ / 128, S_LEN / 128, 1), blk, SMEM>>>(
        kvlat, Wkb, k, KVLORA, KVLORA, KVLORA, EQ, 0, 0, 0);
    // vt = Wvbr @ kv_lat^T    [16384, 1024]  (V transposed, per-head rows)
    gemm_nt<true><<<dim3(S_LEN / 128, EV / 128, 1), blk, SMEM>>>(
        wvbr, kvlat, vt, KVLORA, KVLORA, KVLORA, S_LEN, 0, 0, 0);

    // RoPE on q and k rope sections
    rope_kernel<<<(S_LEN * NHEADS * 32) / 256, 256>>>(q);
    rope_kernel<<<(S_LEN * NHEADS * 32) / 256, 256>>>(k);

    // scores[h] = q_h @ k_h^T   (batched over 128 heads, K=192)
    gemm_nt<false><<<dim3(S_LEN / 128, S_LEN / 128, NHEADS), blk, SMEM>>>(
        q, k, sc, DQd, EQ, EQ, S_LEN,
        (long)DQd, (long)DQd, (long)S_LEN * S_LEN);

    // softmax over each score row (scale fused, rounded output)
    softmax_kernel<<<NHEADS * S_LEN, 256>>>(sc);

    // attn_out[h] = P_h @ vt_h^T   (batched NT: vt_h is [128 d][1024 k])
    gemm_nt<true><<<dim3(DVd / 128, S_LEN / 128, NHEADS), blk, SMEM>>>(
        sc, vt, ao, S_LEN, S_LEN, S_LEN, EV,
        (long)S_LEN * S_LEN, (long)DVd * S_LEN, (long)DVd);

    // out = attn_out @ Wo^T   [1024, 7168]
    gemm_nt<false><<<dim3(DMODEL / 128, S_LEN / 128, 1), blk, SMEM>>>(
        ao, Wo, out, EV, EV, EV, DMODEL, 0, 0, 0);
}